// round 4
// baseline (speedup 1.0000x reference)
#include <cuda_runtime.h>

#define Bn 16
#define Cn 512
#define Hn 64
#define Wn 64
#define Rn 64

// scratch (device globals; allocations are forbidden)
__device__ float g_colpart[Bn*Cn*Wn];   // sum over h
__device__ float g_rowpart[Bn*Cn*Hn];   // sum over w
__device__ float g_gapc[Bn*Cn];
__device__ float g_cout[Bn*Cn*Rn];      // [b][c][r]
__device__ float g_wout[Bn*Rn*Wn];      // [b][r][w]
__device__ float g_houtT[Bn*Hn*Rn];     // [b][h][r]

static __device__ __forceinline__ unsigned long long pk2(float lo, float hi){
  unsigned long long r;
  asm("mov.b64 %0, {%1,%2};" : "=l"(r)
      : "r"(__float_as_uint(lo)), "r"(__float_as_uint(hi)));
  return r;
}
static __device__ __forceinline__ unsigned long long fma2(unsigned long long a,
                                                          unsigned long long b,
                                                          unsigned long long c){
  unsigned long long d;
  asm("fma.rn.f32x2 %0, %1, %2, %3;" : "=l"(d) : "l"(a), "l"(b), "l"(c));
  return d;
}
static __device__ __forceinline__ float hsum2(unsigned long long v){
  unsigned lo, hi;
  asm("mov.b64 {%0,%1}, %2;" : "=r"(lo), "=r"(hi) : "l"(v));
  return __uint_as_float(lo) + __uint_as_float(hi);
}

// ---------------- K1: per-(b,c) plane reductions ----------------
__global__ __launch_bounds__(256) void k1_reduce(const float* __restrict__ x){
  __shared__ float xs[Hn*65];
  __shared__ float part[256];
  const int bc = blockIdx.x;
  const float* p = x + (size_t)bc * (Hn*Wn);
  const int t = threadIdx.x;
  float s = 0.f;
#pragma unroll
  for (int j = 0; j < 16; j++){
    int idx = t + (j << 8);
    float v = p[idx];
    xs[(idx >> 6)*65 + (idx & 63)] = v;
    s += v;
  }
  part[t] = s;
  __syncthreads();
#pragma unroll
  for (int off = 128; off > 0; off >>= 1){
    if (t < off) part[t] += part[t + off];
    __syncthreads();
  }
  if (t == 0) g_gapc[bc] = part[0] * (1.f/4096.f);
  if (t < 64){
    float cs = 0.f;
#pragma unroll
    for (int hh = 0; hh < Hn; hh++) cs += xs[hh*65 + t];
    g_colpart[bc*Wn + t] = cs;
  } else if (t < 128){
    int hh = t - 64;
    float rs = 0.f;
#pragma unroll
    for (int ww = 0; ww < Wn; ww++) rs += xs[hh*65 + ww];
    g_rowpart[bc*Hn + hh] = rs;
  }
}

// ---------------- K2: gap_w/gap_h + conv1d branches ----------------
__global__ __launch_bounds__(256) void k2_branches(
    const float* __restrict__ wc, const float* __restrict__ ac,
    const float* __restrict__ ww, const float* __restrict__ aw,
    const float* __restrict__ wh, const float* __restrict__ ah){
  const int b = blockIdx.x;
  const int t = threadIdx.x;
  __shared__ float gc[Cn+2], gw[Wn+2], gh[Hn+2], red[256];

  for (int i = t; i < Cn; i += 256) gc[i+1] = g_gapc[b*Cn + i];
  if (t == 0){
    gc[0]=0.f; gc[Cn+1]=0.f; gw[0]=0.f; gw[Wn+1]=0.f; gh[0]=0.f; gh[Hn+1]=0.f;
  }
  const int wq = t & 63, pp = t >> 6;
  float s = 0.f;
  for (int c = pp; c < Cn; c += 4) s += g_colpart[(b*Cn + c)*Wn + wq];
  red[t] = s;
  __syncthreads();
  if (t < 64) gw[t+1] = (red[t]+red[t+64]+red[t+128]+red[t+192]) * (1.f/32768.f);
  __syncthreads();
  s = 0.f;
  for (int c = pp; c < Cn; c += 4) s += g_rowpart[(b*Cn + c)*Hn + wq];
  red[t] = s;
  __syncthreads();
  if (t < 64) gh[t+1] = (red[t]+red[t+64]+red[t+128]+red[t+192]) * (1.f/32768.f);
  __syncthreads();

  const float a_c = ac[0], a_w = aw[0], a_h = ah[0];
  for (int i = t; i < Cn*Rn; i += 256){
    int r = i & 63, c = i >> 6;
    float v = wc[3*r]*gc[c] + wc[3*r+1]*gc[c+1] + wc[3*r+2]*gc[c+2];
    g_cout[(b*Cn + c)*Rn + r] = (v >= 0.f) ? v : a_c*v;
  }
  for (int i = t; i < Rn*Wn; i += 256){
    int w_ = i & 63, r = i >> 6;
    float v = ww[3*r]*gw[w_] + ww[3*r+1]*gw[w_+1] + ww[3*r+2]*gw[w_+2];
    g_wout[(b*Rn + r)*Wn + w_] = (v >= 0.f) ? v : a_w*v;
  }
  for (int i = t; i < Hn*Rn; i += 256){
    int r = i & 63, hh = i >> 6;
    float v = wh[3*r]*gh[hh] + wh[3*r+1]*gh[hh+1] + wh[3*r+2]*gh[hh+2];
    g_houtT[(b*Hn + hh)*Rn + r] = (v >= 0.f) ? v : a_h*v;
  }
}

// ---------------- K3: GEMM + softmax + conv3d + residual ----------------
#define SM_CP    0
#define SM_WOUT  32768
#define SM_MH    (SM_WOUT + 4096)
#define SM_RED   (SM_MH + 64)
#define SM_WIN   (SM_RED + 512)
#define SM_FLOATS (SM_WIN + 8*4*3*66)
#define SMEM_BYTES (SM_FLOATS * 4)

__global__ __launch_bounds__(512, 1) void k3_main(
    const float* __restrict__ x, const float* __restrict__ w3d,
    float* __restrict__ out){
  extern __shared__ float sm[];
  float* cp     = sm + SM_CP;     // [512][64] : cout tile, then cp, then gcrw
  float* wout_s = sm + SM_WOUT;   // [64][64]
  float* mh     = sm + SM_MH;     // [64]
  float* red    = sm + SM_RED;    // [512]
  float* win    = sm + SM_WIN;    // [8 groups][4 slots][3 h][66]

  const int t = threadIdx.x;
  const int w = t & 63;
  const int g = t >> 6;
  const int h = blockIdx.x;
  const int b = blockIdx.y;
  const int c0 = g << 6;

  {
    const float4* s1 = (const float4*)(g_cout + (size_t)b*Cn*Rn);
    float4* d1 = (float4*)cp;
    for (int i = t; i < Cn*Rn/4; i += 512) d1[i] = s1[i];
    const float4* s2 = (const float4*)(g_wout + (size_t)b*Rn*Wn);
    float4* d2 = (float4*)wout_s;
    for (int i = t; i < Rn*Wn/4; i += 512) d2[i] = s2[i];
    if (t < 64) mh[t] = g_houtT[(b*Hn + h)*Rn + t];
  }
  __syncthreads();

  unsigned long long m2[32];
#pragma unroll
  for (int j = 0; j < 32; j++){
    float lo = mh[2*j]   * wout_s[(2*j)*64 + w];
    float hi = mh[2*j+1] * wout_s[(2*j+1)*64 + w];
    m2[j] = pk2(lo, hi);
  }

  // in-place GEMM: cp[c][w] = sum_r cout[c][r] * m[r]
  for (int cc = 0; cc < 64; cc++){
    const int c = c0 + cc;
    const unsigned long long* row = (const unsigned long long*)(cp + (c << 6));
    unsigned long long a0 = pk2(0.f,0.f), a1 = a0, a2 = a0, a3 = a0;
#pragma unroll
    for (int j = 0; j < 32; j += 4){
      a0 = fma2(row[j],   m2[j],   a0);
      a1 = fma2(row[j+1], m2[j+1], a1);
      a2 = fma2(row[j+2], m2[j+2], a2);
      a3 = fma2(row[j+3], m2[j+3], a3);
    }
    float v = hsum2(a0) + hsum2(a1) + hsum2(a2) + hsum2(a3);
    __syncthreads();            // all reads of row c done before overwrite
    cp[(c << 6) + w] = v;
  }
  __syncthreads();

  // softmax over c per column w
  float mx = -1e30f;
  for (int cc = 0; cc < 64; cc++) mx = fmaxf(mx, cp[((c0+cc) << 6) + w]);
  red[t] = mx;
  __syncthreads();
  float M = red[w];
#pragma unroll
  for (int j = 1; j < 8; j++) M = fmaxf(M, red[j*64 + w]);
  __syncthreads();
  float se = 0.f;
  for (int cc = 0; cc < 64; cc++){
    int idx = ((c0+cc) << 6) + w;
    float e = __expf(cp[idx] - M);
    cp[idx] = e;
    se += e;
  }
  red[t] = se;
  __syncthreads();
  float S = red[w];
#pragma unroll
  for (int j = 1; j < 8; j++) S += red[j*64 + w];
  float inv = 1.f / S;
  for (int cc = 0; cc < 64; cc++) cp[((c0+cc) << 6) + w] *= inv;

  // conv3d with 4-slot rotating channel window
  float k3d[27];
#pragma unroll
  for (int i = 0; i < 27; i++) k3d[i] = w3d[i];

#pragma unroll
  for (int pre = -1; pre <= 1; pre++){
    int ch = c0 + pre;
    float* dstp = win + ((g*4 + ((ch + 4) & 3))*3)*66;
    for (int i = w; i < 198; i += 64){
      int dh = i / 66, j = i - dh*66;
      int hh = h - 1 + dh, wl = j - 1;
      float v = 0.f;
      if ((unsigned)ch < 512u && (unsigned)hh < 64u && (unsigned)wl < 64u)
        v = x[((size_t)(b*Cn + ch)*64 + hh)*64 + wl];
      dstp[i] = v;
    }
  }
  __syncthreads();

  for (int cc = 0; cc < 64; cc++){
    const int c = c0 + cc;
    float res = 0.f;
#pragma unroll
    for (int dc = 0; dc < 3; dc++){
      const float* base = win + ((g*4 + ((c - 1 + dc + 4) & 3))*3)*66 + w;
#pragma unroll
      for (int dh = 0; dh < 3; dh++){
        const float* rw = base + dh*66;
        res += k3d[dc*9 + dh*3 + 0]*rw[0]
             + k3d[dc*9 + dh*3 + 1]*rw[1]
             + k3d[dc*9 + dh*3 + 2]*rw[2];
      }
    }
    float xv = win[((g*4 + ((c + 4) & 3))*3 + 1)*66 + w + 1]; // x[b][c][h][w]
    out[((size_t)(b*Cn + c)*64 + h)*64 + w] = res * cp[(c << 6) + w] + xv;

    if (cc < 63){
      int ch = c + 2;
      float* dstp = win + ((g*4 + ((ch + 4) & 3))*3)*66;
      for (int i = w; i < 198; i += 64){
        int dh = i / 66, j = i - dh*66;
        int hh = h - 1 + dh, wl = j - 1;
        float v = 0.f;
        if ((unsigned)ch < 512u && (unsigned)hh < 64u && (unsigned)wl < 64u)
          v = x[((size_t)(b*Cn + ch)*64 + hh)*64 + wl];
        dstp[i] = v;
      }
    }
    __syncthreads();
  }
}

extern "C" void kernel_launch(void* const* d_in, const int* in_sizes, int n_in,
                              void* d_out, int out_size){
  const float* x   = (const float*)d_in[0];
  const float* wc  = (const float*)d_in[1];
  const float* ac  = (const float*)d_in[2];
  const float* ww  = (const float*)d_in[3];
  const float* aw  = (const float*)d_in[4];
  const float* wh  = (const float*)d_in[5];
  const float* ah  = (const float*)d_in[6];
  const float* w3d = (const float*)d_in[7];
  float* out = (float*)d_out;

  cudaFuncSetAttribute(k3_main, cudaFuncAttributeMaxDynamicSharedMemorySize,
                       SMEM_BYTES);
  k1_reduce<<<Bn*Cn, 256>>>(x);
  k2_branches<<<Bn, 256>>>(wc, ac, ww, aw, wh, ah);
  k3_main<<<dim3(Hn, Bn), 512, SMEM_BYTES>>>(x, w3d, out);
}

// round 5
// speedup vs baseline: 1.9710x; 1.9710x over previous
#include <cuda_runtime.h>

#define Bn 16
#define Cn 512
#define Hn 64
#define Wn 64
#define Rn 64

// scratch (device globals; allocations are forbidden)
__device__ float g_colpart[Bn*Cn*Wn];   // sum over h
__device__ float g_rowpart[Bn*Cn*Hn];   // sum over w
__device__ float g_gapc[Bn*Cn];
__device__ float g_cout[Bn*Cn*Rn];      // [b][c][r]
__device__ float g_wout[Bn*Rn*Wn];      // [b][r][w]
__device__ float g_houtT[Bn*Hn*Rn];     // [b][h][r]

static __device__ __forceinline__ unsigned long long pk2(float lo, float hi){
  unsigned long long r;
  asm("mov.b64 %0, {%1,%2};" : "=l"(r)
      : "r"(__float_as_uint(lo)), "r"(__float_as_uint(hi)));
  return r;
}
static __device__ __forceinline__ unsigned long long fma2(unsigned long long a,
                                                          unsigned long long b,
                                                          unsigned long long c){
  unsigned long long d;
  asm("fma.rn.f32x2 %0, %1, %2, %3;" : "=l"(d) : "l"(a), "l"(b), "l"(c));
  return d;
}
static __device__ __forceinline__ float hsum2(unsigned long long v){
  unsigned lo, hi;
  asm("mov.b64 {%0,%1}, %2;" : "=r"(lo), "=r"(hi) : "l"(v));
  return __uint_as_float(lo) + __uint_as_float(hi);
}
#define GBAR() asm volatile("bar.sync %0, 64;" :: "r"(g + 1) : "memory")

// ---------------- K1: per-(b,c) plane reductions ----------------
__global__ __launch_bounds__(256) void k1_reduce(const float* __restrict__ x){
  __shared__ float xs[Hn*65];
  __shared__ float part[256];
  const int bc = blockIdx.x;
  const float* p = x + (size_t)bc * (Hn*Wn);
  const int t = threadIdx.x;
  float s = 0.f;
#pragma unroll
  for (int j = 0; j < 16; j++){
    int idx = t + (j << 8);
    float v = p[idx];
    xs[(idx >> 6)*65 + (idx & 63)] = v;
    s += v;
  }
  part[t] = s;
  __syncthreads();
#pragma unroll
  for (int off = 128; off > 0; off >>= 1){
    if (t < off) part[t] += part[t + off];
    __syncthreads();
  }
  if (t == 0) g_gapc[bc] = part[0] * (1.f/4096.f);
  if (t < 64){
    float cs = 0.f;
#pragma unroll
    for (int hh = 0; hh < Hn; hh++) cs += xs[hh*65 + t];
    g_colpart[bc*Wn + t] = cs;
  } else if (t < 128){
    int hh = t - 64;
    float rs = 0.f;
#pragma unroll
    for (int ww = 0; ww < Wn; ww++) rs += xs[hh*65 + ww];
    g_rowpart[bc*Hn + hh] = rs;
  }
}

// ---------------- K2: gap_w/gap_h + conv1d branches ----------------
__global__ __launch_bounds__(256) void k2_branches(
    const float* __restrict__ wc, const float* __restrict__ ac,
    const float* __restrict__ ww, const float* __restrict__ aw,
    const float* __restrict__ wh, const float* __restrict__ ah){
  const int b = blockIdx.x;
  const int t = threadIdx.x;
  __shared__ float gc[Cn+2], gw[Wn+2], gh[Hn+2], red[256];

  for (int i = t; i < Cn; i += 256) gc[i+1] = g_gapc[b*Cn + i];
  if (t == 0){
    gc[0]=0.f; gc[Cn+1]=0.f; gw[0]=0.f; gw[Wn+1]=0.f; gh[0]=0.f; gh[Hn+1]=0.f;
  }
  const int wq = t & 63, pp = t >> 6;
  float s = 0.f;
  for (int c = pp; c < Cn; c += 4) s += g_colpart[(b*Cn + c)*Wn + wq];
  red[t] = s;
  __syncthreads();
  if (t < 64) gw[t+1] = (red[t]+red[t+64]+red[t+128]+red[t+192]) * (1.f/32768.f);
  __syncthreads();
  s = 0.f;
  for (int c = pp; c < Cn; c += 4) s += g_rowpart[(b*Cn + c)*Hn + wq];
  red[t] = s;
  __syncthreads();
  if (t < 64) gh[t+1] = (red[t]+red[t+64]+red[t+128]+red[t+192]) * (1.f/32768.f);
  __syncthreads();

  const float a_c = ac[0], a_w = aw[0], a_h = ah[0];
  for (int i = t; i < Cn*Rn; i += 256){
    int r = i & 63, c = i >> 6;
    float v = wc[3*r]*gc[c] + wc[3*r+1]*gc[c+1] + wc[3*r+2]*gc[c+2];
    g_cout[(b*Cn + c)*Rn + r] = (v >= 0.f) ? v : a_c*v;
  }
  for (int i = t; i < Rn*Wn; i += 256){
    int w_ = i & 63, r = i >> 6;
    float v = ww[3*r]*gw[w_] + ww[3*r+1]*gw[w_+1] + ww[3*r+2]*gw[w_+2];
    g_wout[(b*Rn + r)*Wn + w_] = (v >= 0.f) ? v : a_w*v;
  }
  for (int i = t; i < Hn*Rn; i += 256){
    int r = i & 63, hh = i >> 6;
    float v = wh[3*r]*gh[hh] + wh[3*r+1]*gh[hh+1] + wh[3*r+2]*gh[hh+2];
    g_houtT[(b*Hn + hh)*Rn + r] = (v >= 0.f) ? v : a_h*v;
  }
}

// ---------------- K3: GEMM + softmax + conv3d + residual ----------------
// smem layout (float offsets)
#define SM_CP    0                       // [512][64] cout tile -> cp -> gcrw
#define SM_WOUT  32768                   // [64][64]
#define SM_MH    (SM_WOUT + 4096)        // [64]
#define SM_RED   (SM_MH + 64)            // [512]
#define SM_WIN   (SM_RED + 512)          // [8 groups][4 slots][3*66]
#define SM_FLOATS (SM_WIN + 8*4*198)
#define SMEM_BYTES (SM_FLOATS * 4)

__global__ __launch_bounds__(512, 1) void k3_main(
    const float* __restrict__ x, const float* __restrict__ w3d,
    float* __restrict__ out){
  extern __shared__ float sm[];
  float* cp     = sm + SM_CP;
  float* wout_s = sm + SM_WOUT;
  float* mh     = sm + SM_MH;
  float* red    = sm + SM_RED;
  float* win    = sm + SM_WIN;

  const int t = threadIdx.x;
  const int w = t & 63;
  const int g = t >> 6;
  const int h = blockIdx.x;
  const int b = blockIdx.y;
  const int c0 = g << 6;

  // cooperative tile loads
  {
    const float4* s1 = (const float4*)(g_cout + (size_t)b*Cn*Rn);
    float4* d1 = (float4*)cp;
    for (int i = t; i < Cn*Rn/4; i += 512) d1[i] = s1[i];
    const float4* s2 = (const float4*)(g_wout + (size_t)b*Rn*Wn);
    float4* d2 = (float4*)wout_s;
    for (int i = t; i < Rn*Wn/4; i += 512) d2[i] = s2[i];
    if (t < 64) mh[t] = g_houtT[(b*Hn + h)*Rn + t];
  }
  __syncthreads();

  unsigned long long m2[32];
#pragma unroll
  for (int j = 0; j < 32; j++){
    float lo = mh[2*j]   * wout_s[(2*j)*64 + w];
    float hi = mh[2*j+1] * wout_s[(2*j+1)*64 + w];
    m2[j] = pk2(lo, hi);
  }

  // in-place GEMM, 8 rows per group barrier (rows are group-private)
  for (int chunk = 0; chunk < 64; chunk += 8){
    float v[8];
#pragma unroll
    for (int q = 0; q < 8; q++){
      const ulonglong2* row = (const ulonglong2*)(cp + ((c0 + chunk + q) << 6));
      unsigned long long a0 = pk2(0.f,0.f), a1 = a0, a2 = a0, a3 = a0;
#pragma unroll
      for (int j = 0; j < 16; j += 2){
        ulonglong2 r0 = row[j], r1 = row[j+1];
        a0 = fma2(r0.x, m2[2*j],   a0);
        a1 = fma2(r0.y, m2[2*j+1], a1);
        a2 = fma2(r1.x, m2[2*j+2], a2);
        a3 = fma2(r1.y, m2[2*j+3], a3);
      }
      v[q] = hsum2(a0) + hsum2(a1) + hsum2(a2) + hsum2(a3);
    }
    GBAR();   // all group reads of rows [chunk,chunk+8) done
#pragma unroll
    for (int q = 0; q < 8; q++) cp[((c0 + chunk + q) << 6) + w] = v[q];
  }
  GBAR();     // group writes visible for max pass

  // softmax over c per column w (cross-group reductions need full barriers)
  float mx = -1e30f;
  for (int cc = 0; cc < 64; cc++) mx = fmaxf(mx, cp[((c0+cc) << 6) + w]);
  red[t] = mx;
  __syncthreads();
  float M = red[w];
#pragma unroll
  for (int j = 1; j < 8; j++) M = fmaxf(M, red[j*64 + w]);
  __syncthreads();
  float se = 0.f;
  for (int cc = 0; cc < 64; cc++){
    int idx = ((c0+cc) << 6) + w;
    float e = __expf(cp[idx] - M);
    cp[idx] = e;
    se += e;
  }
  red[t] = se;
  __syncthreads();
  float S = red[w];
#pragma unroll
  for (int j = 1; j < 8; j++) S += red[j*64 + w];
  float inv = 1.f / S;
  for (int cc = 0; cc < 64; cc++) cp[((c0+cc) << 6) + w] *= inv;
  // own-row, own-column writes: conv reads them from the same thread -> no barrier

  // conv3d: 4-slot rotating channel window, distance-2 prefetch, group barriers
  float k3d[27];
#pragma unroll
  for (int i = 0; i < 27; i++) k3d[i] = w3d[i];

  // precompute refill geometry: thread covers i = w + 64k of the 3x66 window
  int goff[4], soff[4];
  bool pv[4];
#pragma unroll
  for (int k = 0; k < 4; k++){
    int i = w + (k << 6);
    int dh = i / 66, j = i - dh*66;
    int hh = h - 1 + dh, wl = j - 1;
    soff[k] = i;
    goff[k] = hh*64 + wl;
    pv[k] = (i < 198) && ((unsigned)hh < 64u) && ((unsigned)wl < 64u);
  }
  const float* xb = x + (size_t)b * Cn * 4096;
  float* wing = win + g*4*198;

  // prologue: channels c0-1, c0, c0+1 to smem; c0+2 into regs
#pragma unroll
  for (int pre = 0; pre < 3; pre++){
    int ch = c0 - 1 + pre;
    float* dst = wing + ((ch + 4) & 3)*198;
#pragma unroll
    for (int k = 0; k < 4; k++){
      int i = w + (k << 6);
      if (i < 198){
        float v = 0.f;
        if (pv[k] && (unsigned)ch < 512u) v = xb[(size_t)ch*4096 + goff[k]];
        dst[i] = v;
      }
    }
  }
  float cur[4];
  {
    int ch = c0 + 2;
#pragma unroll
    for (int k = 0; k < 4; k++)
      cur[k] = (pv[k] && (unsigned)ch < 512u) ? xb[(size_t)ch*4096 + goff[k]] : 0.f;
  }
  GBAR();

  for (int cc = 0; cc < 64; cc++){
    const int c = c0 + cc;
    // prefetch channel c+3 (consumed at iter cc+2)
    float nx[4] = {0.f, 0.f, 0.f, 0.f};
    if (cc <= 61){
      int ch = c + 3;
#pragma unroll
      for (int k = 0; k < 4; k++)
        if (pv[k] && (unsigned)ch < 512u) nx[k] = xb[(size_t)ch*4096 + goff[k]];
    }

    float res = 0.f;
#pragma unroll
    for (int dc = 0; dc < 3; dc++){
      const float* basep = wing + ((c - 1 + dc + 4) & 3)*198 + w;
#pragma unroll
      for (int dh = 0; dh < 3; dh++){
        const float* rw = basep + dh*66;
        res += k3d[dc*9 + dh*3 + 0]*rw[0]
             + k3d[dc*9 + dh*3 + 1]*rw[1]
             + k3d[dc*9 + dh*3 + 2]*rw[2];
      }
    }
    float xv = wing[(c & 3)*198 + 66 + w + 1];          // x[b][c][h][w]
    out[((size_t)(b*Cn + c)*64 + h)*64 + w] = res * cp[(c << 6) + w] + xv;

    // store channel c+2 (loaded at iter cc-1) into its slot
    if (cc <= 62){
      float* dst = wing + ((c + 2) & 3)*198;
#pragma unroll
      for (int k = 0; k < 4; k++){
        int i = w + (k << 6);
        if (i < 198) dst[i] = cur[k];
      }
    }
#pragma unroll
    for (int k = 0; k < 4; k++) cur[k] = nx[k];
    GBAR();
  }
}

extern "C" void kernel_launch(void* const* d_in, const int* in_sizes, int n_in,
                              void* d_out, int out_size){
  const float* x   = (const float*)d_in[0];
  const float* wc  = (const float*)d_in[1];
  const float* ac  = (const float*)d_in[2];
  const float* ww  = (const float*)d_in[3];
  const float* aw  = (const float*)d_in[4];
  const float* wh  = (const float*)d_in[5];
  const float* ah  = (const float*)d_in[6];
  const float* w3d = (const float*)d_in[7];
  float* out = (float*)d_out;

  cudaFuncSetAttribute(k3_main, cudaFuncAttributeMaxDynamicSharedMemorySize,
                       SMEM_BYTES);
  k1_reduce<<<Bn*Cn, 256>>>(x);
  k2_branches<<<Bn, 256>>>(wc, ac, ww, aw, wh, ah);
  k3_main<<<dim3(Hn, Bn), 512, SMEM_BYTES>>>(x, w3d, out);
}